// round 15
// baseline (speedup 1.0000x reference)
#include <cuda_runtime.h>
#include <cuda_bf16.h>
#include <cuda_fp16.h>
#include <math_constants.h>

#define N_NODES 100000
#define N_EDGES 1600000
#define IN_CH   128
#define OUT_CH  64
#define NEG_SLOPE 0.2f
#define EPS_F 1e-10f

#define SCAN_BS 1024
#define NUM_SCAN_BLOCKS ((N_NODES + SCAN_BS - 1) / SCAN_BS)   // 98

// ---------------- scratch (no allocations allowed) ----------------
__device__ __half g_h[(size_t)N_NODES * OUT_CH];  // 12.8 MB (fp16)
__device__ float g_el[N_NODES];
__device__ float g_er[N_NODES];
__device__ int   g_deg[N_NODES];
__device__ int   g_fill[N_NODES];                 // preloaded with rowptr starts
__device__ int   g_rowptr[N_NODES + 1];
__device__ int   g_bsum[NUM_SCAN_BLOCKS];
__device__ int2  g_edge_sorted[N_EDGES];          // (src, er-bits) 12.8 MB

__device__ __forceinline__ float leaky(float v) {
    return v > 0.0f ? v : NEG_SLOPE * v;
}

// ---------------- K0: zero deg ----------------
__global__ void init_kernel() {
    int i = blockIdx.x * blockDim.x + threadIdx.x;
    if (i < N_NODES) g_deg[i] = 0;
}

// ================= gemm: split-bf16 tensor-core GEMM + fused elr =================
#define GEMM_ROWS 64
#define XS_STRIDE 136
#define XS_ELEMS  (GEMM_ROWS * XS_STRIDE)
#define WS_ELEMS  (OUT_CH * XS_STRIDE)
#define GEMM_SMEM_BYTES ((2 * XS_ELEMS + 2 * WS_ELEMS) * 2)   // 69632

__device__ __forceinline__ void store_split4(__nv_bfloat16* hi, __nv_bfloat16* lo,
                                             int idx, float4 v) {
    float f[4] = {v.x, v.y, v.z, v.w};
    unsigned hb[4], lb[4];
#pragma unroll
    for (int j = 0; j < 4; j++) {
        __nv_bfloat16 h = __float2bfloat16_rn(f[j]);
        float hf = __bfloat162float(h);
        __nv_bfloat16 l = __float2bfloat16_rn(f[j] - hf);
        hb[j] = (unsigned)__bfloat16_as_ushort(h);
        lb[j] = (unsigned)__bfloat16_as_ushort(l);
    }
    unsigned* ph = reinterpret_cast<unsigned*>(hi + idx);
    unsigned* pl = reinterpret_cast<unsigned*>(lo + idx);
    ph[0] = hb[0] | (hb[1] << 16);
    ph[1] = hb[2] | (hb[3] << 16);
    pl[0] = lb[0] | (lb[1] << 16);
    pl[1] = lb[2] | (lb[3] << 16);
}

__device__ __forceinline__ void mma16816(float d[4], const unsigned a[4], const unsigned b[2]) {
    asm volatile(
        "mma.sync.aligned.m16n8k16.row.col.f32.bf16.bf16.f32 "
        "{%0,%1,%2,%3}, {%4,%5,%6,%7}, {%8,%9}, {%0,%1,%2,%3};\n"
        : "+f"(d[0]), "+f"(d[1]), "+f"(d[2]), "+f"(d[3])
        : "r"(a[0]), "r"(a[1]), "r"(a[2]), "r"(a[3]), "r"(b[0]), "r"(b[1]));
}

__device__ __forceinline__ void ldsm_x4(unsigned addr, unsigned& r0, unsigned& r1,
                                        unsigned& r2, unsigned& r3) {
    asm volatile("ldmatrix.sync.aligned.m8n8.x4.shared.b16 {%0,%1,%2,%3}, [%4];\n"
                 : "=r"(r0), "=r"(r1), "=r"(r2), "=r"(r3) : "r"(addr));
}

// One full K=128 pass: per kstep 2 LDSM.x4 (A, two m16 tiles) + 1 LDSM.x4 (B) + 4 MMA.
__device__ __forceinline__ void gemm_pass(const __nv_bfloat16* xa, const __nv_bfloat16* wb,
                                          unsigned aoff0, unsigned aoff1, unsigned boff,
                                          float d[2][2][4]) {
    unsigned ab0 = (unsigned)__cvta_generic_to_shared(xa) + aoff0;
    unsigned ab1 = (unsigned)__cvta_generic_to_shared(xa) + aoff1;
    unsigned bb0 = (unsigned)__cvta_generic_to_shared(wb) + boff;
#pragma unroll
    for (int ks = 0; ks < 8; ks++) {
        unsigned a0[4], a1[4], bb[4];
        ldsm_x4(ab0 + ks * 32, a0[0], a0[1], a0[2], a0[3]);
        ldsm_x4(ab1 + ks * 32, a1[0], a1[1], a1[2], a1[3]);
        ldsm_x4(bb0 + ks * 32, bb[0], bb[1], bb[2], bb[3]);
        mma16816(d[0][0], a0, &bb[0]);
        mma16816(d[0][1], a0, &bb[2]);
        mma16816(d[1][0], a1, &bb[0]);
        mma16816(d[1][1], a1, &bb[2]);
    }
}

__global__ __launch_bounds__(256, 3) void gemm_kernel(const float* __restrict__ x,
                                                      const float* __restrict__ W,
                                                      const float* __restrict__ a_l,
                                                      const float* __restrict__ a_r) {
    extern __shared__ __align__(16) char dynsmem[];
    __nv_bfloat16* xs_hi = reinterpret_cast<__nv_bfloat16*>(dynsmem);
    __nv_bfloat16* xs_lo = xs_hi + XS_ELEMS;
    __nv_bfloat16* ws_hi = xs_lo + XS_ELEMS;
    __nv_bfloat16* ws_lo = ws_hi + WS_ELEMS;
    __shared__ float s_el[GEMM_ROWS];
    __shared__ float s_er[GEMM_ROWS];

    int tid = threadIdx.x;
    int row0 = blockIdx.x * GEMM_ROWS;

    if (tid < GEMM_ROWS) { s_el[tid] = 0.0f; s_er[tid] = 0.0f; }

    for (int i = tid; i < GEMM_ROWS * (IN_CH / 4); i += 256) {
        int r  = i >> 5;
        int c4 = (i & 31) << 2;
        int row = row0 + r;
        float4 v = make_float4(0.f, 0.f, 0.f, 0.f);
        if (row < N_NODES) v = *reinterpret_cast<const float4*>(x + (size_t)row * IN_CH + c4);
        store_split4(xs_hi, xs_lo, r * XS_STRIDE + c4, v);
    }
    for (int i = tid; i < OUT_CH * (IN_CH / 4); i += 256) {
        int r  = i >> 5;
        int c4 = (i & 31) << 2;
        float4 v = *reinterpret_cast<const float4*>(W + (size_t)r * IN_CH + c4);
        store_split4(ws_hi, ws_lo, r * XS_STRIDE + c4, v);
    }
    __syncthreads();

    int lane = tid & 31, wid = tid >> 5;
    int wm = wid & 1, wn = wid >> 1;
    int g = lane >> 2, tig = lane & 3;

    // ldmatrix per-lane offsets (bytes)
    int a_row_local = (lane & 7) + ((lane >> 3) & 1) * 8;   // row within m16 tile
    int a_col       = ((lane >> 4) & 1) * 8;                // k-half
    unsigned aoff0 = (unsigned)(((wm * 32 + a_row_local) * XS_STRIDE + a_col) * 2);
    unsigned aoff1 = aoff0 + (unsigned)(16 * XS_STRIDE * 2);
    int b_row = wn * 16 + ((lane >> 4) & 1) * 8 + (lane & 7);  // oc row (ni select)
    int b_col = ((lane >> 3) & 1) * 8;                          // k-half
    unsigned boff = (unsigned)((b_row * XS_STRIDE + b_col) * 2);

    float d[2][2][4];
#pragma unroll
    for (int mi = 0; mi < 2; mi++)
#pragma unroll
        for (int ni = 0; ni < 2; ni++)
#pragma unroll
            for (int q = 0; q < 4; q++) d[mi][ni][q] = 0.0f;

    gemm_pass(xs_hi, ws_hi, aoff0, aoff1, boff, d);
    gemm_pass(xs_lo, ws_hi, aoff0, aoff1, boff, d);
    gemm_pass(xs_hi, ws_lo, aoff0, aoff1, boff, d);

    float alv[2][2], arv[2][2];
#pragma unroll
    for (int ni = 0; ni < 2; ni++) {
        int c = wn * 16 + ni * 8 + tig * 2;
        alv[ni][0] = a_l[c];     alv[ni][1] = a_l[c + 1];
        arv[ni][0] = a_r[c];     arv[ni][1] = a_r[c + 1];
    }

#pragma unroll
    for (int mi = 0; mi < 2; mi++) {
        int r1 = wm * 32 + mi * 16 + g;
        int r2 = r1 + 8;
        int grow1 = row0 + r1, grow2 = row0 + r2;
        float sl1 = 0.f, sr1 = 0.f, sl2 = 0.f, sr2 = 0.f;
#pragma unroll
        for (int ni = 0; ni < 2; ni++) {
            int c = wn * 16 + ni * 8 + tig * 2;
            float d0 = d[mi][ni][0], d1 = d[mi][ni][1];
            float d2 = d[mi][ni][2], d3 = d[mi][ni][3];
            sl1 = fmaf(d0, alv[ni][0], fmaf(d1, alv[ni][1], sl1));
            sr1 = fmaf(d0, arv[ni][0], fmaf(d1, arv[ni][1], sr1));
            sl2 = fmaf(d2, alv[ni][0], fmaf(d3, alv[ni][1], sl2));
            sr2 = fmaf(d2, arv[ni][0], fmaf(d3, arv[ni][1], sr2));
            if (grow1 < N_NODES)
                *reinterpret_cast<__half2*>(g_h + (size_t)grow1 * OUT_CH + c) =
                    __floats2half2_rn(d0, d1);
            if (grow2 < N_NODES)
                *reinterpret_cast<__half2*>(g_h + (size_t)grow2 * OUT_CH + c) =
                    __floats2half2_rn(d2, d3);
        }
#pragma unroll
        for (int m = 1; m < 4; m <<= 1) {
            sl1 += __shfl_xor_sync(0xFFFFFFFFu, sl1, m);
            sr1 += __shfl_xor_sync(0xFFFFFFFFu, sr1, m);
            sl2 += __shfl_xor_sync(0xFFFFFFFFu, sl2, m);
            sr2 += __shfl_xor_sync(0xFFFFFFFFu, sr2, m);
        }
        if (tig == 0) {
            atomicAdd(&s_el[r1], sl1); atomicAdd(&s_er[r1], sr1);
            atomicAdd(&s_el[r2], sl2); atomicAdd(&s_er[r2], sr2);
        }
    }
    __syncthreads();
    if (tid < GEMM_ROWS) {
        int row = row0 + tid;
        if (row < N_NODES) { g_el[row] = s_el[tid]; g_er[row] = s_er[tid]; }
    }
}

// ---------------- hist ----------------
__global__ void hist_kernel(const int* __restrict__ ei) {
    int t = blockIdx.x * blockDim.x + threadIdx.x;
    int e4 = t * 4;
    if (e4 >= N_EDGES) return;
    int4 d = *reinterpret_cast<const int4*>(ei + N_EDGES + e4);
    atomicAdd(&g_deg[d.x], 1);
    atomicAdd(&g_deg[d.y], 1);
    atomicAdd(&g_deg[d.z], 1);
    atomicAdd(&g_deg[d.w], 1);
}

// ---------------- scan a ----------------
__global__ void scan_block_kernel() {
    __shared__ int warp_sums[32];
    int i = blockIdx.x * SCAN_BS + threadIdx.x;
    int lane = threadIdx.x & 31, wid = threadIdx.x >> 5;
    int v = (i < N_NODES) ? g_deg[i] : 0;
    int s = v;
#pragma unroll
    for (int o = 1; o < 32; o <<= 1) {
        int t = __shfl_up_sync(0xFFFFFFFFu, s, o);
        if (lane >= o) s += t;
    }
    if (lane == 31) warp_sums[wid] = s;
    __syncthreads();
    if (wid == 0) {
        int ws = warp_sums[lane];
#pragma unroll
        for (int o = 1; o < 32; o <<= 1) {
            int t = __shfl_up_sync(0xFFFFFFFFu, ws, o);
            if (lane >= o) ws += t;
        }
        warp_sums[lane] = ws;
    }
    __syncthreads();
    int incl = s + (wid > 0 ? warp_sums[wid - 1] : 0);
    if (i < N_NODES) g_rowptr[i + 1] = incl;
    if (threadIdx.x == SCAN_BS - 1) g_bsum[blockIdx.x] = incl;
}

// ---------------- scan b ----------------
__global__ void scan_bsum_kernel() {
    __shared__ int sh[NUM_SCAN_BLOCKS];
    int t = threadIdx.x;
    if (t < NUM_SCAN_BLOCKS) sh[t] = g_bsum[t];
    __syncthreads();
    if (t == 0) {
        int run = 0;
        for (int b = 0; b < NUM_SCAN_BLOCKS; b++) {
            int v = sh[b];
            sh[b] = run;
            run += v;
        }
    }
    __syncthreads();
    if (t < NUM_SCAN_BLOCKS) g_bsum[t] = sh[t];
}

// ---------------- scan c ----------------
__global__ void scan_add_kernel() {
    int i = blockIdx.x * blockDim.x + threadIdx.x;
    if (i < N_NODES) {
        int v = g_rowptr[i + 1] + g_bsum[i >> 10];
        g_rowptr[i + 1] = v;
        if (i + 1 < N_NODES) g_fill[i + 1] = v;
    }
    if (i == 0) { g_rowptr[0] = 0; g_fill[0] = 0; }
}

// ---------------- scatter: store (src, er) CSR-ordered ----------------
__global__ void scatter_kernel(const int* __restrict__ ei) {
    int t = blockIdx.x * blockDim.x + threadIdx.x;
    int e4 = t * 4;
    if (e4 >= N_EDGES) return;
    int4 s = *reinterpret_cast<const int4*>(ei + e4);
    int4 d = *reinterpret_cast<const int4*>(ei + N_EDGES + e4);
#pragma unroll
    for (int j = 0; j < 4; j++) {
        int src = (j == 0) ? s.x : (j == 1) ? s.y : (j == 2) ? s.z : s.w;
        int dst = (j == 0) ? d.x : (j == 1) ? d.y : (j == 2) ? d.z : d.w;
        int pos = atomicAdd(&g_fill[dst], 1);
        g_edge_sorted[pos] = make_int2(src, __float_as_int(g_er[src]));
    }
}

// ---------------- msg: 1 warp/node, half2 per lane, unroll x4 ----------------
// NOTE: max-shift dropped; differs from reference by eps*(e^max-1)/sum ~ 3e-8.
__global__ void msg_kernel(float* __restrict__ out, const float* __restrict__ bias) {
    int gtid = blockIdx.x * blockDim.x + threadIdx.x;
    int node = gtid >> 5;
    int lane = gtid & 31;
    if (node >= N_NODES) return;
    int p   = g_rowptr[node];
    int end = g_rowptr[node + 1];
    float el = g_el[node];
    float accx = 0.0f, accy = 0.0f, wsum = 0.0f;
    const __half2* hbase = reinterpret_cast<const __half2*>(g_h);
    for (; p + 4 <= end; p += 4) {
        int2 e0 = g_edge_sorted[p];
        int2 e1 = g_edge_sorted[p + 1];
        int2 e2 = g_edge_sorted[p + 2];
        int2 e3 = g_edge_sorted[p + 3];
        __half2 v0 = hbase[(size_t)e0.x * (OUT_CH / 2) + lane];
        __half2 v1 = hbase[(size_t)e1.x * (OUT_CH / 2) + lane];
        __half2 v2 = hbase[(size_t)e2.x * (OUT_CH / 2) + lane];
        __half2 v3 = hbase[(size_t)e3.x * (OUT_CH / 2) + lane];
        float w0 = __expf(leaky(el + __int_as_float(e0.y)));
        float w1 = __expf(leaky(el + __int_as_float(e1.y)));
        float w2 = __expf(leaky(el + __int_as_float(e2.y)));
        float w3 = __expf(leaky(el + __int_as_float(e3.y)));
        wsum += (w0 + w1) + (w2 + w3);
        float2 f0 = __half22float2(v0);
        float2 f1 = __half22float2(v1);
        float2 f2 = __half22float2(v2);
        float2 f3 = __half22float2(v3);
        accx = fmaf(w0, f0.x, accx); accy = fmaf(w0, f0.y, accy);
        accx = fmaf(w1, f1.x, accx); accy = fmaf(w1, f1.y, accy);
        accx = fmaf(w2, f2.x, accx); accy = fmaf(w2, f2.y, accy);
        accx = fmaf(w3, f3.x, accx); accy = fmaf(w3, f3.y, accy);
    }
    for (; p < end; p++) {
        int2 e0 = g_edge_sorted[p];
        float w0 = __expf(leaky(el + __int_as_float(e0.y)));
        wsum += w0;
        float2 f0 = __half22float2(hbase[(size_t)e0.x * (OUT_CH / 2) + lane]);
        accx = fmaf(w0, f0.x, accx);
        accy = fmaf(w0, f0.y, accy);
    }
    float inv = 1.0f / (wsum + EPS_F);
    int c = lane * 2;
    *reinterpret_cast<float2*>(out + (size_t)node * OUT_CH + c) =
        make_float2(accx * inv + bias[c], accy * inv + bias[c + 1]);
}

// ---------------- launch ----------------
extern "C" void kernel_launch(void* const* d_in, const int* in_sizes, int n_in,
                              void* d_out, int out_size) {
    const float* x    = (const float*)d_in[0];
    const int*   ei   = (const int*)d_in[1];     // int32 (JAX x64 disabled)
    const float* W    = (const float*)d_in[2];
    const float* a_l  = (const float*)d_in[3];
    const float* a_r  = (const float*)d_in[4];
    const float* bias = (const float*)d_in[5];
    float* out = (float*)d_out;

    (void)in_sizes; (void)n_in; (void)out_size;

    cudaFuncSetAttribute(gemm_kernel, cudaFuncAttributeMaxDynamicSharedMemorySize,
                         GEMM_SMEM_BYTES);

    init_kernel<<<(N_NODES + 255) / 256, 256>>>();                    // 0
    hist_kernel<<<(N_EDGES / 4 + 255) / 256, 256>>>(ei);              // 1
    scan_block_kernel<<<NUM_SCAN_BLOCKS, SCAN_BS>>>();                // 2
    gemm_kernel<<<(N_NODES + GEMM_ROWS - 1) / GEMM_ROWS, 256,
                  GEMM_SMEM_BYTES>>>(x, W, a_l, a_r);                 // 3  <-- profiled
    scan_bsum_kernel<<<1, 128>>>();                                   // 4
    scan_add_kernel<<<(N_NODES + 255) / 256, 256>>>();                // 5
    scatter_kernel<<<(N_EDGES / 4 + 255) / 256, 256>>>(ei);           // 6
    {
        long long threads = (long long)N_NODES * 32;   // 1 warp per node
        int blocks = (int)((threads + 255) / 256);
        msg_kernel<<<blocks, 256>>>(out, bias);                       // 7
    }
}

// round 16
// speedup vs baseline: 1.5277x; 1.5277x over previous
#include <cuda_runtime.h>
#include <cuda_bf16.h>
#include <cuda_fp16.h>
#include <math_constants.h>

#define N_NODES 100000
#define N_EDGES 1600000
#define IN_CH   128
#define OUT_CH  64
#define NEG_SLOPE 0.2f
#define EPS_F 1e-10f

#define SCAN_BS 1024
#define NUM_SCAN_BLOCKS ((N_NODES + SCAN_BS - 1) / SCAN_BS)   // 98

// ---------------- scratch (no allocations allowed) ----------------
__device__ __half g_h[(size_t)N_NODES * OUT_CH];  // 12.8 MB (fp16)
__device__ float g_el[N_NODES];
__device__ float g_er[N_NODES];
__device__ int   g_deg[N_NODES];
__device__ int   g_fill[N_NODES];                 // preloaded with rowptr starts
__device__ int   g_rowptr[N_NODES + 1];
__device__ int   g_bsum[NUM_SCAN_BLOCKS];
__device__ int2  g_edge_sorted[N_EDGES];          // (src, er-bits) 12.8 MB

__device__ __forceinline__ float leaky(float v) {
    return v > 0.0f ? v : NEG_SLOPE * v;
}

// ---------------- K0: zero deg ----------------
__global__ void init_kernel() {
    int i = blockIdx.x * blockDim.x + threadIdx.x;
    if (i < N_NODES) g_deg[i] = 0;
}

// ================= gemm: split-bf16 TC GEMM, hi/lo interleaved, fused elr =========
// Row layout (per 64-elem K row): [h0,h1,l0,l1, h2,h3,l2,l3, ...]; stride 272 elems.
#define GEMM_ROWS 64
#define XS2_STRIDE 272                       // bf16 elems per interleaved row (544 B)
#define XS_ELEMS  (GEMM_ROWS * XS2_STRIDE)   // 17408
#define WS_ELEMS  (OUT_CH * XS2_STRIDE)      // 17408
#define GEMM_SMEM_BYTES ((XS_ELEMS + WS_ELEMS) * 2)   // 69632

__device__ __forceinline__ void store_split4i(__nv_bfloat16* base, int idx, float4 v) {
    float f[4] = {v.x, v.y, v.z, v.w};
    unsigned hb[4], lb[4];
#pragma unroll
    for (int j = 0; j < 4; j++) {
        __nv_bfloat16 h = __float2bfloat16_rn(f[j]);
        float hf = __bfloat162float(h);
        __nv_bfloat16 l = __float2bfloat16_rn(f[j] - hf);
        hb[j] = (unsigned)__bfloat16_as_ushort(h);
        lb[j] = (unsigned)__bfloat16_as_ushort(l);
    }
    uint4 pk;
    pk.x = hb[0] | (hb[1] << 16);   // h0 h1
    pk.y = lb[0] | (lb[1] << 16);   // l0 l1
    pk.z = hb[2] | (hb[3] << 16);   // h2 h3
    pk.w = lb[2] | (lb[3] << 16);   // l2 l3
    *reinterpret_cast<uint4*>(base + idx) = pk;
}

__device__ __forceinline__ void mma16816(float d[4], const unsigned a[4], const unsigned b[2]) {
    asm volatile(
        "mma.sync.aligned.m16n8k16.row.col.f32.bf16.bf16.f32 "
        "{%0,%1,%2,%3}, {%4,%5,%6,%7}, {%8,%9}, {%0,%1,%2,%3};\n"
        : "+f"(d[0]), "+f"(d[1]), "+f"(d[2]), "+f"(d[3])
        : "r"(a[0]), "r"(a[1]), "r"(a[2]), "r"(a[3]), "r"(b[0]), "r"(b[1]));
}

__global__ __launch_bounds__(256, 3) void gemm_kernel(const float* __restrict__ x,
                                                      const float* __restrict__ W,
                                                      const float* __restrict__ a_l,
                                                      const float* __restrict__ a_r) {
    extern __shared__ __align__(16) char dynsmem[];
    __nv_bfloat16* xs = reinterpret_cast<__nv_bfloat16*>(dynsmem);
    __nv_bfloat16* ws = xs + XS_ELEMS;
    __shared__ float s_el[GEMM_ROWS];
    __shared__ float s_er[GEMM_ROWS];

    int tid = threadIdx.x;
    int row0 = blockIdx.x * GEMM_ROWS;

    if (tid < GEMM_ROWS) { s_el[tid] = 0.0f; s_er[tid] = 0.0f; }

    // stage x: interleaved hi/lo
    for (int i = tid; i < GEMM_ROWS * (IN_CH / 4); i += 256) {
        int r  = i >> 5;
        int c4 = (i & 31) << 2;
        int row = row0 + r;
        float4 v = make_float4(0.f, 0.f, 0.f, 0.f);
        if (row < N_NODES) v = *reinterpret_cast<const float4*>(x + (size_t)row * IN_CH + c4);
        store_split4i(xs, r * XS2_STRIDE + 2 * c4, v);
    }
    // stage W: interleaved hi/lo
    for (int i = tid; i < OUT_CH * (IN_CH / 4); i += 256) {
        int r  = i >> 5;
        int c4 = (i & 31) << 2;
        float4 v = *reinterpret_cast<const float4*>(W + (size_t)r * IN_CH + c4);
        store_split4i(ws, r * XS2_STRIDE + 2 * c4, v);
    }
    __syncthreads();

    int lane = tid & 31, wid = tid >> 5;
    int wm = wid & 1, wn = wid >> 1;
    int g = lane >> 2, tig = lane & 3;

    float d[2][2][4];
#pragma unroll
    for (int mi = 0; mi < 2; mi++)
#pragma unroll
        for (int ni = 0; ni < 2; ni++)
#pragma unroll
            for (int q = 0; q < 4; q++) d[mi][ni][q] = 0.0f;

    // element offset of k-pair t within a row: 4*t ; k value 2t.
    // thread's k-pairs: t = tig (k=2tig) and t = tig+4 (k=2tig+8) within each k16.
    const uint2* xs2 = reinterpret_cast<const uint2*>(xs);
    const uint2* ws2 = reinterpret_cast<const uint2*>(ws);
    // uint2 index = element offset / 4? element offset 4t -> byte 8t -> uint2 index t... per row:
    // row elem base r*272 -> uint2 base r*68.
#pragma unroll
    for (int ks = 0; ks < 8; ks++) {
        // pair indices within row for this kstep: base pair = ks*8 (16 k values = 8 pairs)
        int t0 = ks * 8 + tig;       // k-half 0
        int t1 = t0 + 4;             // k-half 1
        unsigned ahi[2][4], alo[2][4];
#pragma unroll
        for (int mi = 0; mi < 2; mi++) {
            int rb = wm * 32 + mi * 16;
            uint2 v00 = xs2[(rb + g)     * 68 + t0];
            uint2 v10 = xs2[(rb + g + 8) * 68 + t0];
            uint2 v01 = xs2[(rb + g)     * 68 + t1];
            uint2 v11 = xs2[(rb + g + 8) * 68 + t1];
            ahi[mi][0] = v00.x; alo[mi][0] = v00.y;
            ahi[mi][1] = v10.x; alo[mi][1] = v10.y;
            ahi[mi][2] = v01.x; alo[mi][2] = v01.y;
            ahi[mi][3] = v11.x; alo[mi][3] = v11.y;
        }
        unsigned bhi[2][2], blo[2][2];
#pragma unroll
        for (int ni = 0; ni < 2; ni++) {
            int oc = wn * 16 + ni * 8 + g;
            uint2 w0 = ws2[oc * 68 + t0];
            uint2 w1 = ws2[oc * 68 + t1];
            bhi[ni][0] = w0.x; blo[ni][0] = w0.y;
            bhi[ni][1] = w1.x; blo[ni][1] = w1.y;
        }
#pragma unroll
        for (int mi = 0; mi < 2; mi++)
#pragma unroll
            for (int ni = 0; ni < 2; ni++) {
                mma16816(d[mi][ni], ahi[mi], bhi[ni]);   // xh*Wh
                mma16816(d[mi][ni], alo[mi], bhi[ni]);   // xl*Wh
                mma16816(d[mi][ni], ahi[mi], blo[ni]);   // xh*Wl
            }
    }

    float alv[2][2], arv[2][2];
#pragma unroll
    for (int ni = 0; ni < 2; ni++) {
        int c = wn * 16 + ni * 8 + tig * 2;
        alv[ni][0] = a_l[c];     alv[ni][1] = a_l[c + 1];
        arv[ni][0] = a_r[c];     arv[ni][1] = a_r[c + 1];
    }

#pragma unroll
    for (int mi = 0; mi < 2; mi++) {
        int r1 = wm * 32 + mi * 16 + g;
        int r2 = r1 + 8;
        int grow1 = row0 + r1, grow2 = row0 + r2;
        float sl1 = 0.f, sr1 = 0.f, sl2 = 0.f, sr2 = 0.f;
#pragma unroll
        for (int ni = 0; ni < 2; ni++) {
            int c = wn * 16 + ni * 8 + tig * 2;
            float d0 = d[mi][ni][0], d1 = d[mi][ni][1];
            float d2 = d[mi][ni][2], d3 = d[mi][ni][3];
            sl1 = fmaf(d0, alv[ni][0], fmaf(d1, alv[ni][1], sl1));
            sr1 = fmaf(d0, arv[ni][0], fmaf(d1, arv[ni][1], sr1));
            sl2 = fmaf(d2, alv[ni][0], fmaf(d3, alv[ni][1], sl2));
            sr2 = fmaf(d2, arv[ni][0], fmaf(d3, arv[ni][1], sr2));
            if (grow1 < N_NODES)
                *reinterpret_cast<__half2*>(g_h + (size_t)grow1 * OUT_CH + c) =
                    __floats2half2_rn(d0, d1);
            if (grow2 < N_NODES)
                *reinterpret_cast<__half2*>(g_h + (size_t)grow2 * OUT_CH + c) =
                    __floats2half2_rn(d2, d3);
        }
#pragma unroll
        for (int m = 1; m < 4; m <<= 1) {
            sl1 += __shfl_xor_sync(0xFFFFFFFFu, sl1, m);
            sr1 += __shfl_xor_sync(0xFFFFFFFFu, sr1, m);
            sl2 += __shfl_xor_sync(0xFFFFFFFFu, sl2, m);
            sr2 += __shfl_xor_sync(0xFFFFFFFFu, sr2, m);
        }
        if (tig == 0) {
            atomicAdd(&s_el[r1], sl1); atomicAdd(&s_er[r1], sr1);
            atomicAdd(&s_el[r2], sl2); atomicAdd(&s_er[r2], sr2);
        }
    }
    __syncthreads();
    if (tid < GEMM_ROWS) {
        int row = row0 + tid;
        if (row < N_NODES) { g_el[row] = s_el[tid]; g_er[row] = s_er[tid]; }
    }
}

// ---------------- hist ----------------
__global__ void hist_kernel(const int* __restrict__ ei) {
    int t = blockIdx.x * blockDim.x + threadIdx.x;
    int e4 = t * 4;
    if (e4 >= N_EDGES) return;
    int4 d = *reinterpret_cast<const int4*>(ei + N_EDGES + e4);
    atomicAdd(&g_deg[d.x], 1);
    atomicAdd(&g_deg[d.y], 1);
    atomicAdd(&g_deg[d.z], 1);
    atomicAdd(&g_deg[d.w], 1);
}

// ---------------- scan a ----------------
__global__ void scan_block_kernel() {
    __shared__ int warp_sums[32];
    int i = blockIdx.x * SCAN_BS + threadIdx.x;
    int lane = threadIdx.x & 31, wid = threadIdx.x >> 5;
    int v = (i < N_NODES) ? g_deg[i] : 0;
    int s = v;
#pragma unroll
    for (int o = 1; o < 32; o <<= 1) {
        int t = __shfl_up_sync(0xFFFFFFFFu, s, o);
        if (lane >= o) s += t;
    }
    if (lane == 31) warp_sums[wid] = s;
    __syncthreads();
    if (wid == 0) {
        int ws = warp_sums[lane];
#pragma unroll
        for (int o = 1; o < 32; o <<= 1) {
            int t = __shfl_up_sync(0xFFFFFFFFu, ws, o);
            if (lane >= o) ws += t;
        }
        warp_sums[lane] = ws;
    }
    __syncthreads();
    int incl = s + (wid > 0 ? warp_sums[wid - 1] : 0);
    if (i < N_NODES) g_rowptr[i + 1] = incl;
    if (threadIdx.x == SCAN_BS - 1) g_bsum[blockIdx.x] = incl;
}

// ---------------- scan b ----------------
__global__ void scan_bsum_kernel() {
    __shared__ int sh[NUM_SCAN_BLOCKS];
    int t = threadIdx.x;
    if (t < NUM_SCAN_BLOCKS) sh[t] = g_bsum[t];
    __syncthreads();
    if (t == 0) {
        int run = 0;
        for (int b = 0; b < NUM_SCAN_BLOCKS; b++) {
            int v = sh[b];
            sh[b] = run;
            run += v;
        }
    }
    __syncthreads();
    if (t < NUM_SCAN_BLOCKS) g_bsum[t] = sh[t];
}

// ---------------- scan c ----------------
__global__ void scan_add_kernel() {
    int i = blockIdx.x * blockDim.x + threadIdx.x;
    if (i < N_NODES) {
        int v = g_rowptr[i + 1] + g_bsum[i >> 10];
        g_rowptr[i + 1] = v;
        if (i + 1 < N_NODES) g_fill[i + 1] = v;
    }
    if (i == 0) { g_rowptr[0] = 0; g_fill[0] = 0; }
}

// ---------------- scatter: store (src, er) CSR-ordered ----------------
__global__ void scatter_kernel(const int* __restrict__ ei) {
    int t = blockIdx.x * blockDim.x + threadIdx.x;
    int e4 = t * 4;
    if (e4 >= N_EDGES) return;
    int4 s = *reinterpret_cast<const int4*>(ei + e4);
    int4 d = *reinterpret_cast<const int4*>(ei + N_EDGES + e4);
#pragma unroll
    for (int j = 0; j < 4; j++) {
        int src = (j == 0) ? s.x : (j == 1) ? s.y : (j == 2) ? s.z : s.w;
        int dst = (j == 0) ? d.x : (j == 1) ? d.y : (j == 2) ? d.z : d.w;
        int pos = atomicAdd(&g_fill[dst], 1);
        g_edge_sorted[pos] = make_int2(src, __float_as_int(g_er[src]));
    }
}

// ---------------- msg: 1 warp/node, half2 per lane, unroll x4 ----------------
// NOTE: max-shift dropped; differs from reference by eps*(e^max-1)/sum ~ 3e-8.
__global__ void msg_kernel(float* __restrict__ out, const float* __restrict__ bias) {
    int gtid = blockIdx.x * blockDim.x + threadIdx.x;
    int node = gtid >> 5;
    int lane = gtid & 31;
    if (node >= N_NODES) return;
    int p   = g_rowptr[node];
    int end = g_rowptr[node + 1];
    float el = g_el[node];
    float accx = 0.0f, accy = 0.0f, wsum = 0.0f;
    const __half2* hbase = reinterpret_cast<const __half2*>(g_h);
    for (; p + 4 <= end; p += 4) {
        int2 e0 = g_edge_sorted[p];
        int2 e1 = g_edge_sorted[p + 1];
        int2 e2 = g_edge_sorted[p + 2];
        int2 e3 = g_edge_sorted[p + 3];
        __half2 v0 = hbase[(size_t)e0.x * (OUT_CH / 2) + lane];
        __half2 v1 = hbase[(size_t)e1.x * (OUT_CH / 2) + lane];
        __half2 v2 = hbase[(size_t)e2.x * (OUT_CH / 2) + lane];
        __half2 v3 = hbase[(size_t)e3.x * (OUT_CH / 2) + lane];
        float w0 = __expf(leaky(el + __int_as_float(e0.y)));
        float w1 = __expf(leaky(el + __int_as_float(e1.y)));
        float w2 = __expf(leaky(el + __int_as_float(e2.y)));
        float w3 = __expf(leaky(el + __int_as_float(e3.y)));
        wsum += (w0 + w1) + (w2 + w3);
        float2 f0 = __half22float2(v0);
        float2 f1 = __half22float2(v1);
        float2 f2 = __half22float2(v2);
        float2 f3 = __half22float2(v3);
        accx = fmaf(w0, f0.x, accx); accy = fmaf(w0, f0.y, accy);
        accx = fmaf(w1, f1.x, accx); accy = fmaf(w1, f1.y, accy);
        accx = fmaf(w2, f2.x, accx); accy = fmaf(w2, f2.y, accy);
        accx = fmaf(w3, f3.x, accx); accy = fmaf(w3, f3.y, accy);
    }
    for (; p < end; p++) {
        int2 e0 = g_edge_sorted[p];
        float w0 = __expf(leaky(el + __int_as_float(e0.y)));
        wsum += w0;
        float2 f0 = __half22float2(hbase[(size_t)e0.x * (OUT_CH / 2) + lane]);
        accx = fmaf(w0, f0.x, accx);
        accy = fmaf(w0, f0.y, accy);
    }
    float inv = 1.0f / (wsum + EPS_F);
    int c = lane * 2;
    *reinterpret_cast<float2*>(out + (size_t)node * OUT_CH + c) =
        make_float2(accx * inv + bias[c], accy * inv + bias[c + 1]);
}

// ---------------- launch ----------------
extern "C" void kernel_launch(void* const* d_in, const int* in_sizes, int n_in,
                              void* d_out, int out_size) {
    const float* x    = (const float*)d_in[0];
    const int*   ei   = (const int*)d_in[1];     // int32 (JAX x64 disabled)
    const float* W    = (const float*)d_in[2];
    const float* a_l  = (const float*)d_in[3];
    const float* a_r  = (const float*)d_in[4];
    const float* bias = (const float*)d_in[5];
    float* out = (float*)d_out;

    (void)in_sizes; (void)n_in; (void)out_size;

    cudaFuncSetAttribute(gemm_kernel, cudaFuncAttributeMaxDynamicSharedMemorySize,
                         GEMM_SMEM_BYTES);

    init_kernel<<<(N_NODES + 255) / 256, 256>>>();                    // 0
    hist_kernel<<<(N_EDGES / 4 + 255) / 256, 256>>>(ei);              // 1
    scan_block_kernel<<<NUM_SCAN_BLOCKS, SCAN_BS>>>();                // 2
    gemm_kernel<<<(N_NODES + GEMM_ROWS - 1) / GEMM_ROWS, 256,
                  GEMM_SMEM_BYTES>>>(x, W, a_l, a_r);                 // 3  <-- profiled
    scan_bsum_kernel<<<1, 128>>>();                                   // 4
    scan_add_kernel<<<(N_NODES + 255) / 256, 256>>>();                // 5
    scatter_kernel<<<(N_EDGES / 4 + 255) / 256, 256>>>(ei);           // 6
    {
        long long threads = (long long)N_NODES * 32;   // 1 warp per node
        int blocks = (int)((threads + 255) / 256);
        msg_kernel<<<blocks, 256>>>(out, bias);                       // 7
    }
}

// round 17
// speedup vs baseline: 1.5712x; 1.0285x over previous
#include <cuda_runtime.h>
#include <cuda_bf16.h>
#include <cuda_fp16.h>
#include <math_constants.h>

#define N_NODES 100000
#define N_EDGES 1600000
#define IN_CH   128
#define OUT_CH  64
#define NEG_SLOPE 0.2f
#define EPS_F 1e-10f

#define SCAN_BS 1024
#define NUM_SCAN_BLOCKS ((N_NODES + SCAN_BS - 1) / SCAN_BS)   // 98

// ---------------- scratch (no allocations allowed) ----------------
__device__ __half g_h[(size_t)N_NODES * OUT_CH];  // 12.8 MB (fp16)
__device__ float g_el[N_NODES];
__device__ float g_er[N_NODES];
__device__ int   g_deg[N_NODES];
__device__ int   g_fill[N_NODES];                 // preloaded with rowptr starts
__device__ int   g_rowptr[N_NODES + 1];
__device__ int   g_bsum[NUM_SCAN_BLOCKS];
__device__ int2  g_edge_sorted[N_EDGES];          // (src, er-bits) 12.8 MB

__device__ __forceinline__ float leaky(float v) {
    return v > 0.0f ? v : NEG_SLOPE * v;
}

// ================= gemm config =================
#define GEMM_ROWS 64
#define XS2_STRIDE 272                       // bf16 elems per interleaved row (544 B)
#define XS_ELEMS  (GEMM_ROWS * XS2_STRIDE)   // 17408
#define WS_ELEMS  (OUT_CH * XS2_STRIDE)      // 17408
#define GEMM_SMEM_BYTES ((XS_ELEMS + WS_ELEMS) * 2)   // 69632

__device__ __nv_bfloat16 g_wsplit[WS_ELEMS];      // pre-split W (interleaved hi/lo), 34.8 KB

__device__ __forceinline__ void store_split4i(__nv_bfloat16* base, int idx, float4 v) {
    float f[4] = {v.x, v.y, v.z, v.w};
    unsigned hb[4], lb[4];
#pragma unroll
    for (int j = 0; j < 4; j++) {
        __nv_bfloat16 h = __float2bfloat16_rn(f[j]);
        float hf = __bfloat162float(h);
        __nv_bfloat16 l = __float2bfloat16_rn(f[j] - hf);
        hb[j] = (unsigned)__bfloat16_as_ushort(h);
        lb[j] = (unsigned)__bfloat16_as_ushort(l);
    }
    uint4 pk;
    pk.x = hb[0] | (hb[1] << 16);   // h0 h1
    pk.y = lb[0] | (lb[1] << 16);   // l0 l1
    pk.z = hb[2] | (hb[3] << 16);   // h2 h3
    pk.w = lb[2] | (lb[3] << 16);   // l2 l3
    *reinterpret_cast<uint4*>(base + idx) = pk;
}

// ---------------- K0: zero deg + pre-split W ----------------
__global__ void init_kernel(const float* __restrict__ W) {
    int i = blockIdx.x * blockDim.x + threadIdx.x;
    if (i < N_NODES) g_deg[i] = 0;
    if (i < OUT_CH * (IN_CH / 4)) {
        int r  = i >> 5;
        int c4 = (i & 31) << 2;
        float4 v = *reinterpret_cast<const float4*>(W + (size_t)r * IN_CH + c4);
        store_split4i(g_wsplit, r * XS2_STRIDE + 2 * c4, v);
    }
}

__device__ __forceinline__ void mma16816(float d[4], const unsigned a[4], const unsigned b[2]) {
    asm volatile(
        "mma.sync.aligned.m16n8k16.row.col.f32.bf16.bf16.f32 "
        "{%0,%1,%2,%3}, {%4,%5,%6,%7}, {%8,%9}, {%0,%1,%2,%3};\n"
        : "+f"(d[0]), "+f"(d[1]), "+f"(d[2]), "+f"(d[3])
        : "r"(a[0]), "r"(a[1]), "r"(a[2]), "r"(a[3]), "r"(b[0]), "r"(b[1]));
}

__global__ __launch_bounds__(256, 3) void gemm_kernel(const float* __restrict__ x,
                                                      const float* __restrict__ a_l,
                                                      const float* __restrict__ a_r) {
    extern __shared__ __align__(16) char dynsmem[];
    __nv_bfloat16* xs = reinterpret_cast<__nv_bfloat16*>(dynsmem);
    __nv_bfloat16* ws = xs + XS_ELEMS;
    __shared__ float s_el[GEMM_ROWS];
    __shared__ float s_er[GEMM_ROWS];

    int tid = threadIdx.x;
    int row0 = blockIdx.x * GEMM_ROWS;

    if (tid < GEMM_ROWS) { s_el[tid] = 0.0f; s_er[tid] = 0.0f; }

    // stage x: interleaved hi/lo (conversion needed — unique per block)
    for (int i = tid; i < GEMM_ROWS * (IN_CH / 4); i += 256) {
        int r  = i >> 5;
        int c4 = (i & 31) << 2;
        int row = row0 + r;
        float4 v = make_float4(0.f, 0.f, 0.f, 0.f);
        if (row < N_NODES) v = *reinterpret_cast<const float4*>(x + (size_t)row * IN_CH + c4);
        store_split4i(xs, r * XS2_STRIDE + 2 * c4, v);
    }
    // stage W: plain copy of pre-split data (no conversion math)
    {
        const uint4* src = reinterpret_cast<const uint4*>(g_wsplit);
        uint4* dst = reinterpret_cast<uint4*>(ws);
        for (int i = tid; i < WS_ELEMS / 8; i += 256) dst[i] = src[i];
    }
    __syncthreads();

    int lane = tid & 31, wid = tid >> 5;
    int wm = wid & 1, wn = wid >> 1;
    int g = lane >> 2, tig = lane & 3;

    float d[2][2][4];
#pragma unroll
    for (int mi = 0; mi < 2; mi++)
#pragma unroll
        for (int ni = 0; ni < 2; ni++)
#pragma unroll
            for (int q = 0; q < 4; q++) d[mi][ni][q] = 0.0f;

    // precomputed per-thread base pointers (uint2 units; row stride = 68 uint2)
    const uint2* xs2 = reinterpret_cast<const uint2*>(xs);
    const uint2* ws2 = reinterpret_cast<const uint2*>(ws);
    const uint2* xa0 = xs2 + (wm * 32 + g)      * 68 + tig;   // mi=0 row g
    const uint2* xa1 = xs2 + (wm * 32 + g + 8)  * 68 + tig;   // mi=0 row g+8
    const uint2* xa2 = xs2 + (wm * 32 + g + 16) * 68 + tig;   // mi=1 row g
    const uint2* xa3 = xs2 + (wm * 32 + g + 24) * 68 + tig;   // mi=1 row g+8
    const uint2* wb0 = ws2 + (wn * 16 + g)      * 68 + tig;   // ni=0
    const uint2* wb1 = ws2 + (wn * 16 + g + 8)  * 68 + tig;   // ni=1

#pragma unroll
    for (int ks = 0; ks < 8; ks++) {
        int t0 = ks * 8;         // constant offsets from bases
        int t1 = t0 + 4;
        unsigned ahi[2][4], alo[2][4];
        {
            uint2 v00 = xa0[t0], v10 = xa1[t0], v01 = xa0[t1], v11 = xa1[t1];
            ahi[0][0] = v00.x; alo[0][0] = v00.y;
            ahi[0][1] = v10.x; alo[0][1] = v10.y;
            ahi[0][2] = v01.x; alo[0][2] = v01.y;
            ahi[0][3] = v11.x; alo[0][3] = v11.y;
        }
        {
            uint2 v00 = xa2[t0], v10 = xa3[t0], v01 = xa2[t1], v11 = xa3[t1];
            ahi[1][0] = v00.x; alo[1][0] = v00.y;
            ahi[1][1] = v10.x; alo[1][1] = v10.y;
            ahi[1][2] = v01.x; alo[1][2] = v01.y;
            ahi[1][3] = v11.x; alo[1][3] = v11.y;
        }
        unsigned bhi[2][2], blo[2][2];
        {
            uint2 w0 = wb0[t0], w1 = wb0[t1];
            bhi[0][0] = w0.x; blo[0][0] = w0.y;
            bhi[0][1] = w1.x; blo[0][1] = w1.y;
            uint2 w2 = wb1[t0], w3 = wb1[t1];
            bhi[1][0] = w2.x; blo[1][0] = w2.y;
            bhi[1][1] = w3.x; blo[1][1] = w3.y;
        }
#pragma unroll
        for (int mi = 0; mi < 2; mi++)
#pragma unroll
            for (int ni = 0; ni < 2; ni++) {
                mma16816(d[mi][ni], ahi[mi], bhi[ni]);   // xh*Wh
                mma16816(d[mi][ni], alo[mi], bhi[ni]);   // xl*Wh
                mma16816(d[mi][ni], ahi[mi], blo[ni]);   // xh*Wl
            }
    }

    float alv[2][2], arv[2][2];
#pragma unroll
    for (int ni = 0; ni < 2; ni++) {
        int c = wn * 16 + ni * 8 + tig * 2;
        alv[ni][0] = a_l[c];     alv[ni][1] = a_l[c + 1];
        arv[ni][0] = a_r[c];     arv[ni][1] = a_r[c + 1];
    }

#pragma unroll
    for (int mi = 0; mi < 2; mi++) {
        int r1 = wm * 32 + mi * 16 + g;
        int r2 = r1 + 8;
        int grow1 = row0 + r1, grow2 = row0 + r2;
        float sl1 = 0.f, sr1 = 0.f, sl2 = 0.f, sr2 = 0.f;
#pragma unroll
        for (int ni = 0; ni < 2; ni++) {
            int c = wn * 16 + ni * 8 + tig * 2;
            float d0 = d[mi][ni][0], d1 = d[mi][ni][1];
            float d2 = d[mi][ni][2], d3 = d[mi][ni][3];
            sl1 = fmaf(d0, alv[ni][0], fmaf(d1, alv[ni][1], sl1));
            sr1 = fmaf(d0, arv[ni][0], fmaf(d1, arv[ni][1], sr1));
            sl2 = fmaf(d2, alv[ni][0], fmaf(d3, alv[ni][1], sl2));
            sr2 = fmaf(d2, arv[ni][0], fmaf(d3, arv[ni][1], sr2));
            if (grow1 < N_NODES)
                *reinterpret_cast<__half2*>(g_h + (size_t)grow1 * OUT_CH + c) =
                    __floats2half2_rn(d0, d1);
            if (grow2 < N_NODES)
                *reinterpret_cast<__half2*>(g_h + (size_t)grow2 * OUT_CH + c) =
                    __floats2half2_rn(d2, d3);
        }
#pragma unroll
        for (int m = 1; m < 4; m <<= 1) {
            sl1 += __shfl_xor_sync(0xFFFFFFFFu, sl1, m);
            sr1 += __shfl_xor_sync(0xFFFFFFFFu, sr1, m);
            sl2 += __shfl_xor_sync(0xFFFFFFFFu, sl2, m);
            sr2 += __shfl_xor_sync(0xFFFFFFFFu, sr2, m);
        }
        if (tig == 0) {
            atomicAdd(&s_el[r1], sl1); atomicAdd(&s_er[r1], sr1);
            atomicAdd(&s_el[r2], sl2); atomicAdd(&s_er[r2], sr2);
        }
    }
    __syncthreads();
    if (tid < GEMM_ROWS) {
        int row = row0 + tid;
        if (row < N_NODES) { g_el[row] = s_el[tid]; g_er[row] = s_er[tid]; }
    }
}

// ---------------- hist ----------------
__global__ void hist_kernel(const int* __restrict__ ei) {
    int t = blockIdx.x * blockDim.x + threadIdx.x;
    int e4 = t * 4;
    if (e4 >= N_EDGES) return;
    int4 d = *reinterpret_cast<const int4*>(ei + N_EDGES + e4);
    atomicAdd(&g_deg[d.x], 1);
    atomicAdd(&g_deg[d.y], 1);
    atomicAdd(&g_deg[d.z], 1);
    atomicAdd(&g_deg[d.w], 1);
}

// ---------------- scan a ----------------
__global__ void scan_block_kernel() {
    __shared__ int warp_sums[32];
    int i = blockIdx.x * SCAN_BS + threadIdx.x;
    int lane = threadIdx.x & 31, wid = threadIdx.x >> 5;
    int v = (i < N_NODES) ? g_deg[i] : 0;
    int s = v;
#pragma unroll
    for (int o = 1; o < 32; o <<= 1) {
        int t = __shfl_up_sync(0xFFFFFFFFu, s, o);
        if (lane >= o) s += t;
    }
    if (lane == 31) warp_sums[wid] = s;
    __syncthreads();
    if (wid == 0) {
        int ws = warp_sums[lane];
#pragma unroll
        for (int o = 1; o < 32; o <<= 1) {
            int t = __shfl_up_sync(0xFFFFFFFFu, ws, o);
            if (lane >= o) ws += t;
        }
        warp_sums[lane] = ws;
    }
    __syncthreads();
    int incl = s + (wid > 0 ? warp_sums[wid - 1] : 0);
    if (i < N_NODES) g_rowptr[i + 1] = incl;
    if (threadIdx.x == SCAN_BS - 1) g_bsum[blockIdx.x] = incl;
}

// ---------------- scan b ----------------
__global__ void scan_bsum_kernel() {
    __shared__ int sh[NUM_SCAN_BLOCKS];
    int t = threadIdx.x;
    if (t < NUM_SCAN_BLOCKS) sh[t] = g_bsum[t];
    __syncthreads();
    if (t == 0) {
        int run = 0;
        for (int b = 0; b < NUM_SCAN_BLOCKS; b++) {
            int v = sh[b];
            sh[b] = run;
            run += v;
        }
    }
    __syncthreads();
    if (t < NUM_SCAN_BLOCKS) g_bsum[t] = sh[t];
}

// ---------------- scan c ----------------
__global__ void scan_add_kernel() {
    int i = blockIdx.x * blockDim.x + threadIdx.x;
    if (i < N_NODES) {
        int v = g_rowptr[i + 1] + g_bsum[i >> 10];
        g_rowptr[i + 1] = v;
        if (i + 1 < N_NODES) g_fill[i + 1] = v;
    }
    if (i == 0) { g_rowptr[0] = 0; g_fill[0] = 0; }
}

// ---------------- scatter: store (src, er) CSR-ordered ----------------
__global__ void scatter_kernel(const int* __restrict__ ei) {
    int t = blockIdx.x * blockDim.x + threadIdx.x;
    int e4 = t * 4;
    if (e4 >= N_EDGES) return;
    int4 s = *reinterpret_cast<const int4*>(ei + e4);
    int4 d = *reinterpret_cast<const int4*>(ei + N_EDGES + e4);
#pragma unroll
    for (int j = 0; j < 4; j++) {
        int src = (j == 0) ? s.x : (j == 1) ? s.y : (j == 2) ? s.z : s.w;
        int dst = (j == 0) ? d.x : (j == 1) ? d.y : (j == 2) ? d.z : d.w;
        int pos = atomicAdd(&g_fill[dst], 1);
        g_edge_sorted[pos] = make_int2(src, __float_as_int(g_er[src]));
    }
}

// ---------------- msg: 1 warp/node, half2 per lane, unroll x8 ----------------
// NOTE: max-shift dropped; differs from reference by eps*(e^max-1)/sum ~ 3e-8.
__global__ void msg_kernel(float* __restrict__ out, const float* __restrict__ bias) {
    int gtid = blockIdx.x * blockDim.x + threadIdx.x;
    int node = gtid >> 5;
    int lane = gtid & 31;
    if (node >= N_NODES) return;
    int p   = g_rowptr[node];
    int end = g_rowptr[node + 1];
    float el = g_el[node];
    float accx = 0.0f, accy = 0.0f, wsum = 0.0f;
    const __half2* hbase = reinterpret_cast<const __half2*>(g_h);
    for (; p + 8 <= end; p += 8) {
        int2 e[8];
        __half2 v[8];
#pragma unroll
        for (int j = 0; j < 8; j++) e[j] = g_edge_sorted[p + j];
#pragma unroll
        for (int j = 0; j < 8; j++) v[j] = hbase[(size_t)e[j].x * (OUT_CH / 2) + lane];
#pragma unroll
        for (int j = 0; j < 8; j++) {
            float w = __expf(leaky(el + __int_as_float(e[j].y)));
            wsum += w;
            float2 f = __half22float2(v[j]);
            accx = fmaf(w, f.x, accx);
            accy = fmaf(w, f.y, accy);
        }
    }
    for (; p + 2 <= end; p += 2) {
        int2 e0 = g_edge_sorted[p];
        int2 e1 = g_edge_sorted[p + 1];
        __half2 v0 = hbase[(size_t)e0.x * (OUT_CH / 2) + lane];
        __half2 v1 = hbase[(size_t)e1.x * (OUT_CH / 2) + lane];
        float w0 = __expf(leaky(el + __int_as_float(e0.y)));
        float w1 = __expf(leaky(el + __int_as_float(e1.y)));
        wsum += w0 + w1;
        float2 f0 = __half22float2(v0);
        float2 f1 = __half22float2(v1);
        accx = fmaf(w0, f0.x, accx); accy = fmaf(w0, f0.y, accy);
        accx = fmaf(w1, f1.x, accx); accy = fmaf(w1, f1.y, accy);
    }
    if (p < end) {
        int2 e0 = g_edge_sorted[p];
        float w0 = __expf(leaky(el + __int_as_float(e0.y)));
        wsum += w0;
        float2 f0 = __half22float2(hbase[(size_t)e0.x * (OUT_CH / 2) + lane]);
        accx = fmaf(w0, f0.x, accx);
        accy = fmaf(w0, f0.y, accy);
    }
    float inv = 1.0f / (wsum + EPS_F);
    int c = lane * 2;
    *reinterpret_cast<float2*>(out + (size_t)node * OUT_CH + c) =
        make_float2(accx * inv + bias[c], accy * inv + bias[c + 1]);
}

// ---------------- launch ----------------
extern "C" void kernel_launch(void* const* d_in, const int* in_sizes, int n_in,
                              void* d_out, int out_size) {
    const float* x    = (const float*)d_in[0];
    const int*   ei   = (const int*)d_in[1];     // int32 (JAX x64 disabled)
    const float* W    = (const float*)d_in[2];
    const float* a_l  = (const float*)d_in[3];
    const float* a_r  = (const float*)d_in[4];
    const float* bias = (const float*)d_in[5];
    float* out = (float*)d_out;

    (void)in_sizes; (void)n_in; (void)out_size;

    cudaFuncSetAttribute(gemm_kernel, cudaFuncAttributeMaxDynamicSharedMemorySize,
                         GEMM_SMEM_BYTES);

    init_kernel<<<(N_NODES + 255) / 256, 256>>>(W);                   // 0
    hist_kernel<<<(N_EDGES / 4 + 255) / 256, 256>>>(ei);              // 1
    scan_block_kernel<<<NUM_SCAN_BLOCKS, SCAN_BS>>>();                // 2
    gemm_kernel<<<(N_NODES + GEMM_ROWS - 1) / GEMM_ROWS, 256,
                  GEMM_SMEM_BYTES>>>(x, a_l, a_r);                    // 3  <-- profiled
    scan_bsum_kernel<<<1, 128>>>();                                   // 4
    scan_add_kernel<<<(N_NODES + 255) / 256, 256>>>();                // 5
    scatter_kernel<<<(N_EDGES / 4 + 255) / 256, 256>>>(ei);           // 6
    {
        long long threads = (long long)N_NODES * 32;   // 1 warp per node
        int blocks = (int)((threads + 255) / 256);
        msg_kernel<<<blocks, 256>>>(out, bias);                       // 7
    }
}